// round 2
// baseline (speedup 1.0000x reference)
#include <cuda_runtime.h>
#include <math.h>
#include <stdint.h>

#define BNUM 32
#define LLT 512
#define LST 128
#define CIN 9
#define HDIM 128
#define RNUM 8
#define KWIN 25
#define PADW 12
#define EPSF 1e-5f
#define OUTC 192   // M*3

// -------- scratch (static device, no allocs) --------
__device__ float d_bufA[BNUM*LLT*HDIM];
__device__ float d_bufB[BNUM*LLT*HDIM];
__device__ float d_est [BNUM*LST*HDIM];
__device__ float d_logits[BNUM*RNUM];
__device__ int   d_regime[BNUM];
__device__ float d_wsel[BNUM];
__device__ float d_partial[BNUM*8*OUTC];

__device__ __forceinline__ float gelu_exact(float x){
    return 0.5f*x*(1.0f+erff(x*0.7071067811865476f));
}

// reduce N independent values across the whole block (NW warps)
template<int N, int NW>
__device__ __forceinline__ void block_reduce_vec(float* v, float* tmp, float* res){
    int tid = threadIdx.x;
    #pragma unroll
    for (int i=0;i<N;i++){
        #pragma unroll
        for (int o=16;o;o>>=1) v[i] += __shfl_xor_sync(0xffffffffu, v[i], o);
    }
    int w = tid>>5, lane = tid&31;
    if (lane==0){
        #pragma unroll
        for (int i=0;i<N;i++) tmp[i*NW+w]=v[i];
    }
    __syncthreads();
    if (tid<N){
        float s=0.f;
        #pragma unroll
        for (int ww=0;ww<NW;ww++) s+=tmp[tid*NW+ww];
        res[tid]=s;
    }
    __syncthreads();
}

// ---------------- encode: x-=x[:,0]; moving avg; two LBR branches ----------------
__global__ void encode_kernel(const float* __restrict__ in,
                              const float* __restrict__ Ws, const float* __restrict__ bs,
                              const float* __restrict__ Wt, const float* __restrict__ bt,
                              float* __restrict__ out, int L){
    int l = blockIdx.x, b = blockIdx.y, h = threadIdx.x;  // 128 threads
    __shared__ float sx[CIN], tx[CIN];
    __shared__ float tmp[2*4];
    __shared__ float res[2], res2[2];
    if (h < CIN){
        int c = h;
        const float* base = in + (size_t)b*L*CIN;
        float x0 = base[c];
        float sum = 0.f;
        #pragma unroll
        for (int w=0; w<KWIN; w++){
            int l2 = l - PADW + w;
            l2 = l2 < 0 ? 0 : (l2 > L-1 ? L-1 : l2);
            sum += base[l2*CIN + c];
        }
        float mm = sum*(1.0f/KWIN) - x0;
        float xc = base[l*CIN + c] - x0;
        sx[c] = xc - mm;   // seasonal
        tx[c] = mm;        // trend
    }
    __syncthreads();
    float s = bs[h], t = bt[h];
    #pragma unroll
    for (int c=0;c<CIN;c++){
        s = fmaf(sx[c], Ws[c*HDIM+h], s);
        t = fmaf(tx[c], Wt[c*HDIM+h], t);
    }
    float v[2]; v[0]=s; v[1]=t;
    block_reduce_vec<2,4>(v,tmp,res);
    float ms = res[0]*(1.0f/HDIM), mt = res[1]*(1.0f/HDIM);
    float ds = s-ms, dt = t-mt;
    v[0]=ds*ds; v[1]=dt*dt;
    block_reduce_vec<2,4>(v,tmp,res2);
    float vs = res2[0]*(1.0f/HDIM), vt = res2[1]*(1.0f/HDIM);
    float y = gelu_exact(ds*rsqrtf(vs+EPSF)) + gelu_exact(dt*rsqrtf(vt+EPSF));
    out[((size_t)b*L + l)*HDIM + h] = y;
}

// ---------------- hidden LBR: (B,L,H)@(H,H) + inorm(H) + gelu, 8 rows/block ----------------
template<int ROWS>
__global__ void hidden_kernel(const float* __restrict__ in, const float* __restrict__ W,
                              const float* __restrict__ bias, float* __restrict__ out, int L){
    int lg = blockIdx.x, b = blockIdx.y, h = threadIdx.x;  // 128 threads
    __shared__ float xs[ROWS*HDIM];
    __shared__ float tmp[ROWS*4];
    __shared__ float res[ROWS], res2[ROWS];
    const float* basein = in + ((size_t)b*L + (size_t)lg*ROWS)*HDIM;
    #pragma unroll
    for (int i=0;i<ROWS;i++) xs[i*HDIM + h] = basein[i*HDIM + h];
    __syncthreads();
    float acc[ROWS];
    float bh = bias[h];
    #pragma unroll
    for (int i=0;i<ROWS;i++) acc[i]=bh;
    #pragma unroll 8
    for (int k=0;k<HDIM;k++){
        float w = W[k*HDIM + h];
        #pragma unroll
        for (int i=0;i<ROWS;i++) acc[i] = fmaf(xs[i*HDIM + k], w, acc[i]);
    }
    float v[ROWS];
    #pragma unroll
    for (int i=0;i<ROWS;i++) v[i]=acc[i];
    block_reduce_vec<ROWS,4>(v,tmp,res);
    float d[ROWS];
    #pragma unroll
    for (int i=0;i<ROWS;i++){ d[i]=acc[i]-res[i]*(1.0f/HDIM); v[i]=d[i]*d[i]; }
    block_reduce_vec<ROWS,4>(v,tmp,res2);
    float* baseout = out + ((size_t)b*L + (size_t)lg*ROWS)*HDIM;
    #pragma unroll
    for (int i=0;i<ROWS;i++)
        baseout[i*HDIM + h] = gelu_exact(d[i]*rsqrtf(res2[i]*(1.0f/HDIM)+EPSF));
}

// ---------------- lookback LBR: swap -> (B,H,Lin)@(Lin,Lout) + inorm(Lout) + gelu -> swap ----------------
// input layout (B,Lin,H); output layout (B,Lout,H). 16 h-rows per block, Lout threads.
template<int LIN, int LOUT>
__global__ void lookback_kernel(const float* __restrict__ in, const float* __restrict__ W,
                                const float* __restrict__ bias, float* __restrict__ out){
    constexpr int NW = LOUT/32;
    int hg = blockIdx.x, b = blockIdx.y, j = threadIdx.x;
    __shared__ float xs[LIN*16];
    __shared__ float tmp[16*NW];
    __shared__ float res[16], res2[16];
    const float* basein = in + (size_t)b*LIN*HDIM + hg*16;
    for (int idx=j; idx<LIN*16; idx+=LOUT){
        int l = idx>>4, hh = idx&15;
        xs[idx] = basein[(size_t)l*HDIM + hh];
    }
    __syncthreads();
    float acc[16];
    float bj = bias[j];
    #pragma unroll
    for (int i=0;i<16;i++) acc[i]=bj;
    #pragma unroll 4
    for (int l=0;l<LIN;l++){
        float w = W[(size_t)l*LOUT + j];
        #pragma unroll
        for (int i=0;i<16;i++) acc[i] = fmaf(xs[l*16+i], w, acc[i]);
    }
    float v[16];
    #pragma unroll
    for (int i=0;i<16;i++) v[i]=acc[i];
    block_reduce_vec<16,NW>(v,tmp,res);
    float d[16];
    #pragma unroll
    for (int i=0;i<16;i++){ d[i]=acc[i]-res[i]*(1.0f/LOUT); v[i]=d[i]*d[i]; }
    block_reduce_vec<16,NW>(v,tmp,res2);
    float o[16];
    #pragma unroll
    for (int i=0;i<16;i++) o[i] = gelu_exact(d[i]*rsqrtf(res2[i]*(1.0f/LOUT)+EPSF));
    float4* po = (float4*)(out + ((size_t)b*LOUT + j)*HDIM + hg*16);
    po[0] = make_float4(o[0],o[1],o[2],o[3]);
    po[1] = make_float4(o[4],o[5],o[6],o[7]);
    po[2] = make_float4(o[8],o[9],o[10],o[11]);
    po[3] = make_float4(o[12],o[13],o[14],o[15]);
}

// ---------------- logits: (B,8192) @ (8192,8) + br ----------------
__global__ void logits_kernel(const float* __restrict__ o, const float* __restrict__ Wr,
                              const float* __restrict__ br, float* __restrict__ logits){
    int b = blockIdx.x, tid = threadIdx.x;  // 256 threads
    float acc[8];
    #pragma unroll
    for (int r=0;r<8;r++) acc[r]=0.f;
    for (int i=tid; i<8192; i+=256){
        float x = o[(size_t)b*8192 + i];
        const float4* w4 = reinterpret_cast<const float4*>(Wr + (size_t)i*8);
        float4 wa = w4[0], wb = w4[1];
        acc[0]=fmaf(x,wa.x,acc[0]); acc[1]=fmaf(x,wa.y,acc[1]);
        acc[2]=fmaf(x,wa.z,acc[2]); acc[3]=fmaf(x,wa.w,acc[3]);
        acc[4]=fmaf(x,wb.x,acc[4]); acc[5]=fmaf(x,wb.y,acc[5]);
        acc[6]=fmaf(x,wb.z,acc[6]); acc[7]=fmaf(x,wb.w,acc[7]);
    }
    __shared__ float sh[8*8];
    #pragma unroll
    for (int r=0;r<8;r++){
        #pragma unroll
        for (int o2=16;o2;o2>>=1) acc[r] += __shfl_xor_sync(0xffffffffu, acc[r], o2);
    }
    int w=tid>>5, lane=tid&31;
    if (lane==0){
        #pragma unroll
        for (int r=0;r<8;r++) sh[r*8+w]=acc[r];
    }
    __syncthreads();
    if (tid<8){
        float s=br[tid];
        #pragma unroll
        for (int ww=0;ww<8;ww++) s+=sh[tid*8+ww];
        logits[b*8+tid]=s;
    }
}

// ---------------- exact JAX threefry2x32 (PARTITIONABLE mode) gumbel + hard select ----------------
// JAX >= 0.5 default: jax_threefry_partitionable=True. random_bits(shape) hashes each
// flat index i elementwise: (h0,h1) = threefry2x32(key, (hi32(i)=0, lo32(i)=i)),
// bits[i] = h0 ^ h1. Then uniform = bitcast((bits>>9)|0x3f800000)-1, clamped to
// [tiny, 1), gumbel = -log(-log(u)).
__device__ __forceinline__ uint32_t rotl32(uint32_t x,int r){ return (x<<r)|(x>>(32-r)); }
__device__ __forceinline__ float gumbel_from_bits(uint32_t bits){
    const float tiny = 1.17549435e-38f;
    float f = __uint_as_float((bits>>9)|0x3f800000u) - 1.0f;
    float u = fmaxf(tiny, f + tiny);   // uniform(tiny, 1) per jax (maxval-minval rounds to 1.0f)
    return -logf(-logf(u));
}
__global__ void gumbel_kernel(const float* __restrict__ logits,
                              int* __restrict__ regime, float* __restrict__ wsel){
    __shared__ float g[256];
    int tid = threadIdx.x;  // 256 threads
    {
        uint32_t x0 = 0u, x1 = (uint32_t)tid;     // 64-bit flat counter (hi=0, lo=i)
        const uint32_t k0=0u, k1=42u, k2=k0^k1^0x1BD11BDAu;
        x0+=k0; x1+=k1;
        #define TFR(r) { x0+=x1; x1=rotl32(x1,r); x1^=x0; }
        TFR(13)TFR(15)TFR(26)TFR(6)   x0+=k1; x1+=k2+1u;
        TFR(17)TFR(29)TFR(16)TFR(24)  x0+=k2; x1+=k0+2u;
        TFR(13)TFR(15)TFR(26)TFR(6)   x0+=k0; x1+=k1+3u;
        TFR(17)TFR(29)TFR(16)TFR(24)  x0+=k1; x1+=k2+4u;
        TFR(13)TFR(15)TFR(26)TFR(6)   x0+=k2; x1+=k0+5u;
        #undef TFR
        g[tid] = gumbel_from_bits(x0 ^ x1);       // xor-fold the 2x32 output
    }
    __syncthreads();
    if (tid < BNUM){
        float z[8];
        #pragma unroll
        for (int r=0;r<8;r++) z[r] = logits[tid*8+r] + g[tid*8+r];  // TAU=1
        float mx = z[0]; int am = 0;
        #pragma unroll
        for (int r=1;r<8;r++) if (z[r] > mx){ mx=z[r]; am=r; }
        float sum=0.f;
        #pragma unroll
        for (int r=0;r<8;r++) sum += expf(z[r]-mx);
        float y = 1.0f/sum;                  // y_soft at argmax
        wsel[tid] = (1.0f - y) + y;          // straight-through value
        regime[tid] = am;
    }
}

// ---------------- final contraction: out[b,t] += e_st[b,n,h]*proto[r_b,n,h,t] ----------------
__global__ void final_partial(const float* __restrict__ est, const float* __restrict__ proto,
                              const int* __restrict__ regime, float* __restrict__ partial){
    int chunk = blockIdx.x, b = blockIdx.y, t = threadIdx.x;  // 192 threads
    __shared__ float es[16*HDIM];
    int n0 = chunk*16;
    for (int idx=t; idx<16*HDIM; idx+=OUTC)
        es[idx] = est[((size_t)b*LST + n0)*HDIM + idx];
    __syncthreads();
    int r = regime[b];
    const float* p = proto + (((size_t)r*LST + n0)*HDIM)*OUTC + t;
    float acc = 0.f;
    #pragma unroll 8
    for (int nh=0; nh<16*HDIM; nh++){
        acc = fmaf(es[nh], __ldg(p), acc);
        p += OUTC;
    }
    partial[((size_t)b*8 + chunk)*OUTC + t] = acc;
}

__global__ void final_softmax(const float* __restrict__ partial, const float* __restrict__ wsel,
                              float* __restrict__ out){
    int b = blockIdx.x, t = threadIdx.x;  // 192 threads = 6 warps
    float s = 0.f;
    #pragma unroll
    for (int ch=0; ch<8; ch++) s += partial[((size_t)b*8+ch)*OUTC + t];
    s *= wsel[b];
    __shared__ float shm[6], shs[6];
    float m = s;
    #pragma unroll
    for (int o=16;o;o>>=1) m = fmaxf(m, __shfl_xor_sync(0xffffffffu, m, o));
    if ((t&31)==0) shm[t>>5]=m;
    __syncthreads();
    m = shm[0];
    #pragma unroll
    for (int w=1;w<6;w++) m = fmaxf(m, shm[w]);
    float e = expf(s-m);
    float su = e;
    #pragma unroll
    for (int o=16;o;o>>=1) su += __shfl_xor_sync(0xffffffffu, su, o);
    if ((t&31)==0) shs[t>>5]=su;
    __syncthreads();
    su = 0.f;
    #pragma unroll
    for (int w=0;w<6;w++) su += shs[w];
    out[(size_t)b*OUTC + t] = e/su;
}

// ---------------- launch ----------------
extern "C" void kernel_launch(void* const* d_in, const int* in_sizes, int n_in,
                              void* d_out, int out_size){
    (void)in_sizes; (void)n_in; (void)out_size;
    const float* in_lt = (const float*)d_in[0];
    const float* in_st = (const float*)d_in[1];
    const float* Ws  = (const float*)d_in[2];  const float* bs  = (const float*)d_in[3];
    const float* Wt  = (const float*)d_in[4];  const float* bt  = (const float*)d_in[5];
    const float* Wh1 = (const float*)d_in[6];  const float* bh1 = (const float*)d_in[7];
    const float* Wl1 = (const float*)d_in[8];  const float* bl1 = (const float*)d_in[9];
    const float* Wh2 = (const float*)d_in[10]; const float* bh2 = (const float*)d_in[11];
    const float* Wl2 = (const float*)d_in[12]; const float* bl2 = (const float*)d_in[13];
    const float* Wh3 = (const float*)d_in[14]; const float* bh3 = (const float*)d_in[15];
    const float* Wl3 = (const float*)d_in[16]; const float* bl3 = (const float*)d_in[17];
    const float* Wr  = (const float*)d_in[18]; const float* br  = (const float*)d_in[19];
    const float* proto = (const float*)d_in[20];

    float *bufA, *bufB, *est, *logits, *wsel, *partial; int* regime;
    cudaGetSymbolAddress((void**)&bufA,    d_bufA);
    cudaGetSymbolAddress((void**)&bufB,    d_bufB);
    cudaGetSymbolAddress((void**)&est,     d_est);
    cudaGetSymbolAddress((void**)&logits,  d_logits);
    cudaGetSymbolAddress((void**)&regime,  d_regime);
    cudaGetSymbolAddress((void**)&wsel,    d_wsel);
    cudaGetSymbolAddress((void**)&partial, d_partial);

    encode_kernel<<<dim3(LLT,BNUM), HDIM>>>(in_lt, Ws, bs, Wt, bt, bufA, LLT);
    encode_kernel<<<dim3(LST,BNUM), HDIM>>>(in_st, Ws, bs, Wt, bt, est,  LST);

    hidden_kernel<8><<<dim3(LLT/8,BNUM), HDIM>>>(bufA, Wh1, bh1, bufB, LLT);
    lookback_kernel<512,256><<<dim3(8,BNUM), 256>>>(bufB, Wl1, bl1, bufA);
    hidden_kernel<8><<<dim3(256/8,BNUM), HDIM>>>(bufA, Wh2, bh2, bufB, 256);
    lookback_kernel<256,128><<<dim3(8,BNUM), 128>>>(bufB, Wl2, bl2, bufA);
    hidden_kernel<8><<<dim3(128/8,BNUM), HDIM>>>(bufA, Wh3, bh3, bufB, 128);
    lookback_kernel<128,64><<<dim3(8,BNUM), 64>>>(bufB, Wl3, bl3, bufA);

    logits_kernel<<<BNUM, 256>>>(bufA, Wr, br, logits);
    gumbel_kernel<<<1, 256>>>(logits, regime, wsel);

    final_partial<<<dim3(8,BNUM), OUTC>>>(est, proto, regime, partial);
    final_softmax<<<BNUM, OUTC>>>(partial, wsel, (float*)d_out);
}

// round 3
// speedup vs baseline: 1.3978x; 1.3978x over previous
#include <cuda_runtime.h>
#include <math.h>
#include <stdint.h>

#define BNUM 32
#define LLT 512
#define LST 128
#define CIN 9
#define HDIM 128
#define RNUM 8
#define KWIN 25
#define PADW 12
#define EPSF 1e-5f
#define OUTC 192   // M*3
#define NHTOT 16384  // LST*HDIM
#define NCHUNK 64    // nh chunks of 256

// -------- scratch (static device, no allocs) --------
__device__ float d_bufA[BNUM*LLT*HDIM];
__device__ float d_bufB[BNUM*LLT*HDIM];
__device__ float d_est [BNUM*LST*HDIM];
__device__ float d_logits[BNUM*RNUM];
__device__ float d_wsel[BNUM];
__device__ int   d_rcount[RNUM];
__device__ int   d_rlist[RNUM*BNUM];
__device__ float d_partial[BNUM*NCHUNK*OUTC];

// -------- f32x2 packed math helpers --------
__device__ __forceinline__ uint64_t pack2(float lo, float hi){
    uint64_t d;
    asm("mov.b64 %0, {%1, %2};" : "=l"(d)
        : "r"(__float_as_uint(lo)), "r"(__float_as_uint(hi)));
    return d;
}
__device__ __forceinline__ void unpack2(uint64_t v, float& lo, float& hi){
    uint32_t a, b;
    asm("mov.b64 {%0, %1}, %2;" : "=r"(a), "=r"(b) : "l"(v));
    lo = __uint_as_float(a); hi = __uint_as_float(b);
}
__device__ __forceinline__ void ffma2(uint64_t& d, uint64_t a, uint64_t b, uint64_t c){
    asm("fma.rn.f32x2 %0, %1, %2, %3;" : "=l"(d) : "l"(a), "l"(b), "l"(c));
}

__device__ __forceinline__ float gelu_exact(float x){
    return 0.5f*x*(1.0f+erff(x*0.7071067811865476f));
}

// reduce N independent values across the whole block (NW warps)
template<int N, int NW>
__device__ __forceinline__ void block_reduce_vec(float* v, float* tmp, float* res){
    int tid = threadIdx.x;
    #pragma unroll
    for (int i=0;i<N;i++){
        #pragma unroll
        for (int o=16;o;o>>=1) v[i] += __shfl_xor_sync(0xffffffffu, v[i], o);
    }
    int w = tid>>5, lane = tid&31;
    if (lane==0){
        #pragma unroll
        for (int i=0;i<N;i++) tmp[i*NW+w]=v[i];
    }
    __syncthreads();
    if (tid<N){
        float s=0.f;
        #pragma unroll
        for (int ww=0;ww<NW;ww++) s+=tmp[tid*NW+ww];
        res[tid]=s;
    }
    __syncthreads();
}

// ---------------- encode: x-=x[:,0]; moving avg; two LBR branches ----------------
__global__ void encode_kernel(const float* __restrict__ in,
                              const float* __restrict__ Ws, const float* __restrict__ bs,
                              const float* __restrict__ Wt, const float* __restrict__ bt,
                              float* __restrict__ out, int L){
    int l = blockIdx.x, b = blockIdx.y, h = threadIdx.x;  // 128 threads
    __shared__ float sx[CIN], tx[CIN];
    __shared__ float tmp[2*4];
    __shared__ float res[2], res2[2];
    if (h < CIN){
        int c = h;
        const float* base = in + (size_t)b*L*CIN;
        float x0 = base[c];
        float sum = 0.f;
        #pragma unroll
        for (int w=0; w<KWIN; w++){
            int l2 = l - PADW + w;
            l2 = l2 < 0 ? 0 : (l2 > L-1 ? L-1 : l2);
            sum += base[l2*CIN + c];
        }
        float mm = sum*(1.0f/KWIN) - x0;
        float xc = base[l*CIN + c] - x0;
        sx[c] = xc - mm;   // seasonal
        tx[c] = mm;        // trend
    }
    __syncthreads();
    float s = bs[h], t = bt[h];
    #pragma unroll
    for (int c=0;c<CIN;c++){
        s = fmaf(sx[c], Ws[c*HDIM+h], s);
        t = fmaf(tx[c], Wt[c*HDIM+h], t);
    }
    float v[2]; v[0]=s; v[1]=t;
    block_reduce_vec<2,4>(v,tmp,res);
    float ms = res[0]*(1.0f/HDIM), mt = res[1]*(1.0f/HDIM);
    float ds = s-ms, dt = t-mt;
    v[0]=ds*ds; v[1]=dt*dt;
    block_reduce_vec<2,4>(v,tmp,res2);
    float vs = res2[0]*(1.0f/HDIM), vt = res2[1]*(1.0f/HDIM);
    float y = gelu_exact(ds*rsqrtf(vs+EPSF)) + gelu_exact(dt*rsqrtf(vt+EPSF));
    out[((size_t)b*L + l)*HDIM + h] = y;
}

// ---------------- hidden LBR: (B,L,H)@(H,H) + inorm(H) + gelu, 16 rows/block, f32x2 ----------------
__global__ void hidden_kernel(const float* __restrict__ in, const float* __restrict__ W,
                              const float* __restrict__ bias, float* __restrict__ out, int L){
    constexpr int ROWS = 16, PR = 8;
    int lg = blockIdx.x, b = blockIdx.y, h = threadIdx.x;  // 128 threads
    __shared__ __align__(16) uint64_t xs2[HDIM*PR];        // [k][pair i] 8KB
    __shared__ float tmp[ROWS*4];
    __shared__ float res[ROWS], res2[ROWS];
    const float* basein = in + ((size_t)b*L + (size_t)lg*ROWS)*HDIM;
    // transpose: thread h owns column k=h, writes i-major pairs
    float* xsF = (float*)xs2;
    #pragma unroll
    for (int i=0;i<ROWS;i++) xsF[h*ROWS + i] = basein[i*HDIM + h];
    __syncthreads();
    uint64_t acc[PR];
    float bh = bias[h];
    uint64_t bp = pack2(bh, bh);
    #pragma unroll
    for (int p=0;p<PR;p++) acc[p]=bp;
    #pragma unroll 4
    for (int k=0;k<HDIM;k++){
        float w = W[k*HDIM + h];
        uint64_t wp = pack2(w, w);
        const uint64_t* row = xs2 + k*PR;
        #pragma unroll
        for (int p=0;p<PR;p++) ffma2(acc[p], row[p], wp, acc[p]);
    }
    float val[ROWS], v[ROWS];
    #pragma unroll
    for (int p=0;p<PR;p++) unpack2(acc[p], val[2*p], val[2*p+1]);
    #pragma unroll
    for (int i=0;i<ROWS;i++) v[i]=val[i];
    block_reduce_vec<ROWS,4>(v,tmp,res);
    float d[ROWS];
    #pragma unroll
    for (int i=0;i<ROWS;i++){ d[i]=val[i]-res[i]*(1.0f/HDIM); v[i]=d[i]*d[i]; }
    block_reduce_vec<ROWS,4>(v,tmp,res2);
    float* baseout = out + ((size_t)b*L + (size_t)lg*ROWS)*HDIM;
    #pragma unroll
    for (int i=0;i<ROWS;i++)
        baseout[i*HDIM + h] = gelu_exact(d[i]*rsqrtf(res2[i]*(1.0f/HDIM)+EPSF));
}

// ---------------- lookback LBR: (B,H,Lin)@(Lin,Lout) + inorm(Lout) + gelu ----------------
// G row-groups of 8 h each per block; blockDim = G*LOUT = 256. f32x2 packed over h-pairs.
template<int LIN, int LOUT, int G>
__global__ void lookback_kernel(const float* __restrict__ in, const float* __restrict__ W,
                                const float* __restrict__ bias, float* __restrict__ out){
    constexpr int NW = LOUT/32;
    int hg = blockIdx.x, b = blockIdx.y;
    int tid = threadIdx.x;
    int g = tid / LOUT, j = tid % LOUT;
    __shared__ __align__(16) uint64_t xs2[LIN*G*4];   // [l][g][pair]
    __shared__ float tmp[G*8*NW];
    __shared__ float res[G*8], res2[G*8];
    const float* basein = in + (size_t)b*LIN*HDIM;
    int hbase_blk = hg*(8*G);
    for (int idx=tid; idx<LIN*G*4; idx += G*LOUT){
        int l = idx/(4*G); int r = idx%(4*G);
        int h = hbase_blk + (r>>2)*8 + (r&3)*2;
        float2 v2 = *(const float2*)(basein + (size_t)l*HDIM + h);
        xs2[idx] = pack2(v2.x, v2.y);
    }
    __syncthreads();
    uint64_t acc[4];
    float bj = bias[j];
    uint64_t bp = pack2(bj, bj);
    #pragma unroll
    for (int p=0;p<4;p++) acc[p]=bp;
    const uint64_t* xbase = xs2 + g*4;
    #pragma unroll 4
    for (int l=0;l<LIN;l++){
        float w = W[(size_t)l*LOUT + j];
        uint64_t wp = pack2(w, w);
        const uint64_t* row = xbase + l*(4*G);
        #pragma unroll
        for (int p=0;p<4;p++) ffma2(acc[p], row[p], wp, acc[p]);
    }
    float val[8], v[8];
    #pragma unroll
    for (int p=0;p<4;p++) unpack2(acc[p], val[2*p], val[2*p+1]);
    // group-local reduce (rows of this group reduce over its LOUT threads)
    #pragma unroll
    for (int i=0;i<8;i++){
        v[i]=val[i];
        #pragma unroll
        for (int o=16;o;o>>=1) v[i] += __shfl_xor_sync(0xffffffffu, v[i], o);
    }
    int w0 = tid>>5, wg = w0 % NW;
    if ((tid&31)==0){
        #pragma unroll
        for (int i=0;i<8;i++) tmp[(g*8+i)*NW + wg] = v[i];
    }
    __syncthreads();
    if (tid < G*8){
        float s=0.f;
        #pragma unroll
        for (int ww=0;ww<NW;ww++) s+=tmp[tid*NW+ww];
        res[tid]=s;
    }
    __syncthreads();
    float d[8];
    #pragma unroll
    for (int i=0;i<8;i++){
        d[i]=val[i]-res[g*8+i]*(1.0f/LOUT);
        v[i]=d[i]*d[i];
        #pragma unroll
        for (int o=16;o;o>>=1) v[i] += __shfl_xor_sync(0xffffffffu, v[i], o);
    }
    if ((tid&31)==0){
        #pragma unroll
        for (int i=0;i<8;i++) tmp[(g*8+i)*NW + wg] = v[i];
    }
    __syncthreads();
    if (tid < G*8){
        float s=0.f;
        #pragma unroll
        for (int ww=0;ww<NW;ww++) s+=tmp[tid*NW+ww];
        res2[tid]=s;
    }
    __syncthreads();
    float o8[8];
    #pragma unroll
    for (int i=0;i<8;i++)
        o8[i] = gelu_exact(d[i]*rsqrtf(res2[g*8+i]*(1.0f/LOUT)+EPSF));
    float* po = out + ((size_t)b*LOUT + j)*HDIM + hbase_blk + g*8;
    ((float4*)po)[0] = make_float4(o8[0],o8[1],o8[2],o8[3]);
    ((float4*)po)[1] = make_float4(o8[4],o8[5],o8[6],o8[7]);
}

// ---------------- logits: (B,8192) @ (8192,8) + br ----------------
__global__ void logits_kernel(const float* __restrict__ o, const float* __restrict__ Wr,
                              const float* __restrict__ br, float* __restrict__ logits){
    int b = blockIdx.x, tid = threadIdx.x;  // 256 threads
    float acc[8];
    #pragma unroll
    for (int r=0;r<8;r++) acc[r]=0.f;
    for (int i=tid; i<8192; i+=256){
        float x = o[(size_t)b*8192 + i];
        const float4* w4 = reinterpret_cast<const float4*>(Wr + (size_t)i*8);
        float4 wa = w4[0], wb = w4[1];
        acc[0]=fmaf(x,wa.x,acc[0]); acc[1]=fmaf(x,wa.y,acc[1]);
        acc[2]=fmaf(x,wa.z,acc[2]); acc[3]=fmaf(x,wa.w,acc[3]);
        acc[4]=fmaf(x,wb.x,acc[4]); acc[5]=fmaf(x,wb.y,acc[5]);
        acc[6]=fmaf(x,wb.z,acc[6]); acc[7]=fmaf(x,wb.w,acc[7]);
    }
    __shared__ float sh[8*8];
    #pragma unroll
    for (int r=0;r<8;r++){
        #pragma unroll
        for (int o2=16;o2;o2>>=1) acc[r] += __shfl_xor_sync(0xffffffffu, acc[r], o2);
    }
    int w=tid>>5, lane=tid&31;
    if (lane==0){
        #pragma unroll
        for (int r=0;r<8;r++) sh[r*8+w]=acc[r];
    }
    __syncthreads();
    if (tid<8){
        float s=br[tid];
        #pragma unroll
        for (int ww=0;ww<8;ww++) s+=sh[tid*8+ww];
        logits[b*8+tid]=s;
    }
}

// ---------------- exact JAX threefry2x32 (partitionable) gumbel + hard select + regime lists ----------------
__device__ __forceinline__ uint32_t rotl32(uint32_t x,int r){ return (x<<r)|(x>>(32-r)); }
__device__ __forceinline__ float gumbel_from_bits(uint32_t bits){
    const float tiny = 1.17549435e-38f;
    float f = __uint_as_float((bits>>9)|0x3f800000u) - 1.0f;
    float u = fmaxf(tiny, f + tiny);
    return -logf(-logf(u));
}
__global__ void gumbel_kernel(const float* __restrict__ logits,
                              float* __restrict__ wsel,
                              int* __restrict__ rcount, int* __restrict__ rlist){
    __shared__ float g[256];
    __shared__ int sreg[BNUM];
    int tid = threadIdx.x;  // 256 threads
    {
        uint32_t x0 = 0u, x1 = (uint32_t)tid;
        const uint32_t k0=0u, k1=42u, k2=k0^k1^0x1BD11BDAu;
        x0+=k0; x1+=k1;
        #define TFR(r) { x0+=x1; x1=rotl32(x1,r); x1^=x0; }
        TFR(13)TFR(15)TFR(26)TFR(6)   x0+=k1; x1+=k2+1u;
        TFR(17)TFR(29)TFR(16)TFR(24)  x0+=k2; x1+=k0+2u;
        TFR(13)TFR(15)TFR(26)TFR(6)   x0+=k0; x1+=k1+3u;
        TFR(17)TFR(29)TFR(16)TFR(24)  x0+=k1; x1+=k2+4u;
        TFR(13)TFR(15)TFR(26)TFR(6)   x0+=k2; x1+=k0+5u;
        #undef TFR
        g[tid] = gumbel_from_bits(x0 ^ x1);
    }
    __syncthreads();
    if (tid < BNUM){
        float z[8];
        #pragma unroll
        for (int r=0;r<8;r++) z[r] = logits[tid*8+r] + g[tid*8+r];  // TAU=1
        float mx = z[0]; int am = 0;
        #pragma unroll
        for (int r=1;r<8;r++) if (z[r] > mx){ mx=z[r]; am=r; }
        float sum=0.f;
        #pragma unroll
        for (int r=0;r<8;r++) sum += expf(z[r]-mx);
        float y = 1.0f/sum;
        wsel[tid] = (1.0f - y) + y;
        sreg[tid] = am;
    }
    __syncthreads();
    if (tid == 0){
        int cnt[RNUM];
        #pragma unroll
        for (int r=0;r<RNUM;r++) cnt[r]=0;
        for (int b=0;b<BNUM;b++){
            int r = sreg[b];
            rlist[r*BNUM + cnt[r]] = b;
            cnt[r]++;
        }
        #pragma unroll
        for (int r=0;r<RNUM;r++) rcount[r]=cnt[r];
    }
}

// ---------------- final contraction, regime-grouped, f32x2 over batch pairs ----------------
template<int NP>
__device__ __forceinline__ void fp_body(const uint64_t* __restrict__ es2,
                                        const float* __restrict__ P,
                                        float* __restrict__ partial,
                                        const int* __restrict__ bl,
                                        int nb, int chunk, int t){
    uint64_t acc[NP];
    #pragma unroll
    for (int q=0;q<NP;q++) acc[q]=0ull;
    #pragma unroll 4
    for (int nh=0; nh<256; nh++){
        float pv = P[(size_t)nh*OUTC];
        uint64_t pp = pack2(pv, pv);
        const uint64_t* row = es2 + nh*16;
        #pragma unroll
        for (int q=0;q<NP;q++) ffma2(acc[q], row[q], pp, acc[q]);
    }
    #pragma unroll
    for (int q=0;q<NP;q++){
        float lo, hi; unpack2(acc[q], lo, hi);
        partial[((size_t)bl[2*q]*NCHUNK + chunk)*OUTC + t] = lo;
        if (2*q+1 < nb)
            partial[((size_t)bl[2*q+1]*NCHUNK + chunk)*OUTC + t] = hi;
    }
}

__global__ void final_partial(const float* __restrict__ est, const float* __restrict__ proto,
                              const int* __restrict__ rcount, const int* __restrict__ rlist,
                              float* __restrict__ partial){
    int chunk = blockIdx.x, r = blockIdx.y, t = threadIdx.x;  // 192 threads
    int nb = rcount[r];
    if (nb == 0) return;
    int npair = (nb+1)>>1;
    __shared__ __align__(16) uint64_t es2[256*16];   // [nh][pair] 32KB
    __shared__ int bl[BNUM];
    if (t < BNUM) bl[t] = rlist[r*BNUM + t];
    __syncthreads();
    int nh0 = chunk*256;
    for (int q=0;q<npair;q++){
        int b0 = bl[2*q];
        bool has1 = (2*q+1) < nb;
        const float* e0 = est + (size_t)b0*NHTOT + nh0;
        const float* e1 = has1 ? est + (size_t)bl[2*q+1]*NHTOT + nh0 : e0;
        for (int nh=t; nh<256; nh+=192){
            float lo = e0[nh];
            float hi = has1 ? e1[nh] : 0.f;
            es2[nh*16+q] = pack2(lo, hi);
        }
    }
    __syncthreads();
    const float* P = proto + ((size_t)r*NHTOT + nh0)*OUTC + t;
    switch(npair){
        case 1:  fp_body<1>(es2,P,partial,bl,nb,chunk,t); break;
        case 2:  fp_body<2 >(es2,P,partial,bl,nb,chunk,t); break;
        case 3:  fp_body<3 >(es2,P,partial,bl,nb,chunk,t); break;
        case 4:  fp_body<4 >(es2,P,partial,bl,nb,chunk,t); break;
        case 5:  fp_body<5 >(es2,P,partial,bl,nb,chunk,t); break;
        case 6:  fp_body<6 >(es2,P,partial,bl,nb,chunk,t); break;
        case 7:  fp_body<7 >(es2,P,partial,bl,nb,chunk,t); break;
        case 8:  fp_body<8 >(es2,P,partial,bl,nb,chunk,t); break;
        case 9:  fp_body<9 >(es2,P,partial,bl,nb,chunk,t); break;
        case 10: fp_body<10>(es2,P,partial,bl,nb,chunk,t); break;
        case 11: fp_body<11>(es2,P,partial,bl,nb,chunk,t); break;
        case 12: fp_body<12>(es2,P,partial,bl,nb,chunk,t); break;
        case 13: fp_body<13>(es2,P,partial,bl,nb,chunk,t); break;
        case 14: fp_body<14>(es2,P,partial,bl,nb,chunk,t); break;
        case 15: fp_body<15>(es2,P,partial,bl,nb,chunk,t); break;
        default: fp_body<16>(es2,P,partial,bl,nb,chunk,t); break;
    }
}

__global__ void final_softmax(const float* __restrict__ partial, const float* __restrict__ wsel,
                              float* __restrict__ out){
    int b = blockIdx.x, t = threadIdx.x;  // 192 threads = 6 warps
    float s = 0.f;
    #pragma unroll 8
    for (int ch=0; ch<NCHUNK; ch++) s += partial[((size_t)b*NCHUNK+ch)*OUTC + t];
    s *= wsel[b];
    __shared__ float shm[6], shs[6];
    float m = s;
    #pragma unroll
    for (int o=16;o;o>>=1) m = fmaxf(m, __shfl_xor_sync(0xffffffffu, m, o));
    if ((t&31)==0) shm[t>>5]=m;
    __syncthreads();
    m = shm[0];
    #pragma unroll
    for (int w=1;w<6;w++) m = fmaxf(m, shm[w]);
    float e = expf(s-m);
    float su = e;
    #pragma unroll
    for (int o=16;o;o>>=1) su += __shfl_xor_sync(0xffffffffu, su, o);
    if ((t&31)==0) shs[t>>5]=su;
    __syncthreads();
    su = 0.f;
    #pragma unroll
    for (int w=0;w<6;w++) su += shs[w];
    out[(size_t)b*OUTC + t] = e/su;
}

// ---------------- launch ----------------
extern "C" void kernel_launch(void* const* d_in, const int* in_sizes, int n_in,
                              void* d_out, int out_size){
    (void)in_sizes; (void)n_in; (void)out_size;
    const float* in_lt = (const float*)d_in[0];
    const float* in_st = (const float*)d_in[1];
    const float* Ws  = (const float*)d_in[2];  const float* bs  = (const float*)d_in[3];
    const float* Wt  = (const float*)d_in[4];  const float* bt  = (const float*)d_in[5];
    const float* Wh1 = (const float*)d_in[6];  const float* bh1 = (const float*)d_in[7];
    const float* Wl1 = (const float*)d_in[8];  const float* bl1 = (const float*)d_in[9];
    const float* Wh2 = (const float*)d_in[10]; const float* bh2 = (const float*)d_in[11];
    const float* Wl2 = (const float*)d_in[12]; const float* bl2 = (const float*)d_in[13];
    const float* Wh3 = (const float*)d_in[14]; const float* bh3 = (const float*)d_in[15];
    const float* Wl3 = (const float*)d_in[16]; const float* bl3 = (const float*)d_in[17];
    const float* Wr  = (const float*)d_in[18]; const float* br  = (const float*)d_in[19];
    const float* proto = (const float*)d_in[20];

    float *bufA, *bufB, *est, *logits, *wsel, *partial; int *rcount, *rlist;
    cudaGetSymbolAddress((void**)&bufA,    d_bufA);
    cudaGetSymbolAddress((void**)&bufB,    d_bufB);
    cudaGetSymbolAddress((void**)&est,     d_est);
    cudaGetSymbolAddress((void**)&logits,  d_logits);
    cudaGetSymbolAddress((void**)&wsel,    d_wsel);
    cudaGetSymbolAddress((void**)&rcount,  d_rcount);
    cudaGetSymbolAddress((void**)&rlist,   d_rlist);
    cudaGetSymbolAddress((void**)&partial, d_partial);

    encode_kernel<<<dim3(LLT,BNUM), HDIM>>>(in_lt, Ws, bs, Wt, bt, bufA, LLT);
    encode_kernel<<<dim3(LST,BNUM), HDIM>>>(in_st, Ws, bs, Wt, bt, est,  LST);

    hidden_kernel<<<dim3(LLT/16,BNUM), HDIM>>>(bufA, Wh1, bh1, bufB, LLT);
    lookback_kernel<512,256,1><<<dim3(16,BNUM), 256>>>(bufB, Wl1, bl1, bufA);
    hidden_kernel<<<dim3(256/16,BNUM), HDIM>>>(bufA, Wh2, bh2, bufB, 256);
    lookback_kernel<256,128,2><<<dim3(8,BNUM), 256>>>(bufB, Wl2, bl2, bufA);
    hidden_kernel<<<dim3(128/16,BNUM), HDIM>>>(bufA, Wh3, bh3, bufB, 128);
    lookback_kernel<128,64,4><<<dim3(4,BNUM), 256>>>(bufB, Wl3, bl3, bufA);

    logits_kernel<<<BNUM, 256>>>(bufA, Wr, br, logits);
    gumbel_kernel<<<1, 256>>>(logits, wsel, rcount, rlist);

    final_partial<<<dim3(NCHUNK,RNUM), OUTC>>>(est, proto, rcount, rlist, partial);
    final_softmax<<<BNUM, OUTC>>>(partial, wsel, (float*)d_out);
}

// round 4
// speedup vs baseline: 1.6680x; 1.1933x over previous
#include <cuda_runtime.h>
#include <math.h>
#include <stdint.h>

#define BNUM 32
#define LLT 512
#define LST 128
#define CIN 9
#define HDIM 128
#define RNUM 8
#define KWIN 25
#define PADW 12
#define EPSF 1e-5f
#define OUTC 192   // M*3
#define NHTOT 16384  // LST*HDIM
#define NCHUNK 64    // nh chunks of 256

// -------- scratch (static device, no allocs) --------
__device__ float d_bufA[BNUM*LLT*HDIM];
__device__ float d_bufB[BNUM*LLT*HDIM];
__device__ float d_est [BNUM*LST*HDIM];
__device__ float d_logits[BNUM*RNUM];
__device__ float d_wsel[BNUM];
__device__ int   d_rcount[RNUM];
__device__ int   d_rlist[RNUM*BNUM];
__device__ float d_partial[BNUM*NCHUNK*OUTC];

// -------- f32x2 packed math helpers --------
__device__ __forceinline__ uint64_t pack2(float lo, float hi){
    uint64_t d;
    asm("mov.b64 %0, {%1, %2};" : "=l"(d)
        : "r"(__float_as_uint(lo)), "r"(__float_as_uint(hi)));
    return d;
}
__device__ __forceinline__ void unpack2(uint64_t v, float& lo, float& hi){
    uint32_t a, b;
    asm("mov.b64 {%0, %1}, %2;" : "=r"(a), "=r"(b) : "l"(v));
    lo = __uint_as_float(a); hi = __uint_as_float(b);
}
__device__ __forceinline__ void ffma2(uint64_t& d, uint64_t a, uint64_t b, uint64_t c){
    asm("fma.rn.f32x2 %0, %1, %2, %3;" : "=l"(d) : "l"(a), "l"(b), "l"(c));
}

__device__ __forceinline__ float gelu_exact(float x){
    return 0.5f*x*(1.0f+erff(x*0.7071067811865476f));
}

// reduce N independent values across the whole block (NW warps)
template<int N, int NW>
__device__ __forceinline__ void block_reduce_vec(float* v, float* tmp, float* res){
    int tid = threadIdx.x;
    #pragma unroll
    for (int i=0;i<N;i++){
        #pragma unroll
        for (int o=16;o;o>>=1) v[i] += __shfl_xor_sync(0xffffffffu, v[i], o);
    }
    int w = tid>>5, lane = tid&31;
    if (lane==0){
        #pragma unroll
        for (int i=0;i<N;i++) tmp[i*NW+w]=v[i];
    }
    __syncthreads();
    if (tid<N){
        float s=0.f;
        #pragma unroll
        for (int ww=0;ww<NW;ww++) s+=tmp[tid*NW+ww];
        res[tid]=s;
    }
    __syncthreads();
}

// ---------------- encode: x-=x[:,0]; moving avg; two LBR branches ----------------
__global__ void encode_kernel(const float* __restrict__ in,
                              const float* __restrict__ Ws, const float* __restrict__ bs,
                              const float* __restrict__ Wt, const float* __restrict__ bt,
                              float* __restrict__ out, int L){
    int l = blockIdx.x, b = blockIdx.y, h = threadIdx.x;  // 128 threads
    __shared__ float sx[CIN], tx[CIN];
    __shared__ float tmp[2*4];
    __shared__ float res[2], res2[2];
    if (h < CIN){
        int c = h;
        const float* base = in + (size_t)b*L*CIN;
        float x0 = base[c];
        float sum = 0.f;
        #pragma unroll
        for (int w=0; w<KWIN; w++){
            int l2 = l - PADW + w;
            l2 = l2 < 0 ? 0 : (l2 > L-1 ? L-1 : l2);
            sum += base[l2*CIN + c];
        }
        float mm = sum*(1.0f/KWIN) - x0;
        float xc = base[l*CIN + c] - x0;
        sx[c] = xc - mm;   // seasonal
        tx[c] = mm;        // trend
    }
    __syncthreads();
    float s = bs[h], t = bt[h];
    #pragma unroll
    for (int c=0;c<CIN;c++){
        s = fmaf(sx[c], Ws[c*HDIM+h], s);
        t = fmaf(tx[c], Wt[c*HDIM+h], t);
    }
    float v[2]; v[0]=s; v[1]=t;
    block_reduce_vec<2,4>(v,tmp,res);
    float ms = res[0]*(1.0f/HDIM), mt = res[1]*(1.0f/HDIM);
    float ds = s-ms, dt = t-mt;
    v[0]=ds*ds; v[1]=dt*dt;
    block_reduce_vec<2,4>(v,tmp,res2);
    float vs = res2[0]*(1.0f/HDIM), vt = res2[1]*(1.0f/HDIM);
    float y = gelu_exact(ds*rsqrtf(vs+EPSF)) + gelu_exact(dt*rsqrtf(vt+EPSF));
    out[((size_t)b*L + l)*HDIM + h] = y;
}

// ---------------- hidden LBR: (B,L,H)@(H,H) + inorm(H) + gelu, 8 rows/block, f32x2 ----------------
__global__ void hidden_kernel(const float* __restrict__ in, const float* __restrict__ W,
                              const float* __restrict__ bias, float* __restrict__ out, int L){
    constexpr int ROWS = 8, PR = 4;
    int lg = blockIdx.x, b = blockIdx.y, h = threadIdx.x;  // 128 threads
    __shared__ __align__(16) uint64_t xs2[HDIM*PR];        // [k][pair i] 4KB
    __shared__ float tmp[ROWS*4];
    __shared__ float res[ROWS], res2[ROWS];
    const float* basein = in + ((size_t)b*L + (size_t)lg*ROWS)*HDIM;
    // transpose: thread h owns column k=h, writes i-major pairs
    float* xsF = (float*)xs2;
    #pragma unroll
    for (int i=0;i<ROWS;i++) xsF[h*ROWS + i] = basein[i*HDIM + h];
    __syncthreads();
    uint64_t acc[PR];
    float bh = bias[h];
    uint64_t bp = pack2(bh, bh);
    #pragma unroll
    for (int p=0;p<PR;p++) acc[p]=bp;
    #pragma unroll 8
    for (int k=0;k<HDIM;k++){
        float w = W[k*HDIM + h];
        uint64_t wp = pack2(w, w);
        const uint64_t* row = xs2 + k*PR;
        #pragma unroll
        for (int p=0;p<PR;p++) ffma2(acc[p], row[p], wp, acc[p]);
    }
    float val[ROWS], v[ROWS];
    #pragma unroll
    for (int p=0;p<PR;p++) unpack2(acc[p], val[2*p], val[2*p+1]);
    #pragma unroll
    for (int i=0;i<ROWS;i++) v[i]=val[i];
    block_reduce_vec<ROWS,4>(v,tmp,res);
    float d[ROWS];
    #pragma unroll
    for (int i=0;i<ROWS;i++){ d[i]=val[i]-res[i]*(1.0f/HDIM); v[i]=d[i]*d[i]; }
    block_reduce_vec<ROWS,4>(v,tmp,res2);
    float* baseout = out + ((size_t)b*L + (size_t)lg*ROWS)*HDIM;
    #pragma unroll
    for (int i=0;i<ROWS;i++)
        baseout[i*HDIM + h] = gelu_exact(d[i]*rsqrtf(res2[i]*(1.0f/HDIM)+EPSF));
}

// ---------------- lookback LBR: (B,H,Lin)@(Lin,Lout) + inorm(Lout) + gelu ----------------
// G row-groups of 4 h each per block; blockDim = G*LOUT = 256. f32x2 packed over h-pairs.
template<int LIN, int LOUT, int G>
__global__ void lookback_kernel(const float* __restrict__ in, const float* __restrict__ W,
                                const float* __restrict__ bias, float* __restrict__ out){
    constexpr int NW = LOUT/32;
    int hg = blockIdx.x, b = blockIdx.y;
    int tid = threadIdx.x;
    int g = tid / LOUT, j = tid % LOUT;
    __shared__ __align__(16) uint64_t xs2[LIN*G*2];   // [l][g][pair]  LIN*G*16 bytes
    __shared__ float tmp[G*4*NW];
    __shared__ float res[G*4], res2[G*4];
    const float* basein = in + (size_t)b*LIN*HDIM;
    int hbase_blk = hg*(4*G);
    for (int idx=tid; idx<LIN*G*2; idx += G*LOUT){
        int l = idx/(2*G); int r = idx%(2*G);
        int h = hbase_blk + (r>>1)*4 + (r&1)*2;
        float2 v2 = *(const float2*)(basein + (size_t)l*HDIM + h);
        xs2[idx] = pack2(v2.x, v2.y);
    }
    __syncthreads();
    uint64_t acc[2];
    float bj = bias[j];
    uint64_t bp = pack2(bj, bj);
    acc[0]=bp; acc[1]=bp;
    const uint64_t* xbase = xs2 + g*2;
    #pragma unroll 8
    for (int l=0;l<LIN;l++){
        float w = W[(size_t)l*LOUT + j];
        uint64_t wp = pack2(w, w);
        const uint64_t* row = xbase + l*(2*G);
        ffma2(acc[0], row[0], wp, acc[0]);
        ffma2(acc[1], row[1], wp, acc[1]);
    }
    float val[4], v[4];
    unpack2(acc[0], val[0], val[1]);
    unpack2(acc[1], val[2], val[3]);
    // group-local reduce (rows of this group reduce over its LOUT threads)
    #pragma unroll
    for (int i=0;i<4;i++){
        v[i]=val[i];
        #pragma unroll
        for (int o=16;o;o>>=1) v[i] += __shfl_xor_sync(0xffffffffu, v[i], o);
    }
    int w0 = tid>>5, wg = w0 % NW;
    if ((tid&31)==0){
        #pragma unroll
        for (int i=0;i<4;i++) tmp[(g*4+i)*NW + wg] = v[i];
    }
    __syncthreads();
    if (tid < G*4){
        float s=0.f;
        #pragma unroll
        for (int ww=0;ww<NW;ww++) s+=tmp[tid*NW+ww];
        res[tid]=s;
    }
    __syncthreads();
    float d[4];
    #pragma unroll
    for (int i=0;i<4;i++){
        d[i]=val[i]-res[g*4+i]*(1.0f/LOUT);
        v[i]=d[i]*d[i];
        #pragma unroll
        for (int o=16;o;o>>=1) v[i] += __shfl_xor_sync(0xffffffffu, v[i], o);
    }
    if ((tid&31)==0){
        #pragma unroll
        for (int i=0;i<4;i++) tmp[(g*4+i)*NW + wg] = v[i];
    }
    __syncthreads();
    if (tid < G*4){
        float s=0.f;
        #pragma unroll
        for (int ww=0;ww<NW;ww++) s+=tmp[tid*NW+ww];
        res2[tid]=s;
    }
    __syncthreads();
    float o4[4];
    #pragma unroll
    for (int i=0;i<4;i++)
        o4[i] = gelu_exact(d[i]*rsqrtf(res2[g*4+i]*(1.0f/LOUT)+EPSF));
    float* po = out + ((size_t)b*LOUT + j)*HDIM + hbase_blk + g*4;
    ((float4*)po)[0] = make_float4(o4[0],o4[1],o4[2],o4[3]);
}

// ---------------- logits: (B,8192) @ (8192,8) + br ----------------
__global__ void logits_kernel(const float* __restrict__ o, const float* __restrict__ Wr,
                              const float* __restrict__ br, float* __restrict__ logits){
    int b = blockIdx.x, tid = threadIdx.x;  // 256 threads
    float acc[8];
    #pragma unroll
    for (int r=0;r<8;r++) acc[r]=0.f;
    for (int i=tid; i<8192; i+=256){
        float x = o[(size_t)b*8192 + i];
        const float4* w4 = reinterpret_cast<const float4*>(Wr + (size_t)i*8);
        float4 wa = w4[0], wb = w4[1];
        acc[0]=fmaf(x,wa.x,acc[0]); acc[1]=fmaf(x,wa.y,acc[1]);
        acc[2]=fmaf(x,wa.z,acc[2]); acc[3]=fmaf(x,wa.w,acc[3]);
        acc[4]=fmaf(x,wb.x,acc[4]); acc[5]=fmaf(x,wb.y,acc[5]);
        acc[6]=fmaf(x,wb.z,acc[6]); acc[7]=fmaf(x,wb.w,acc[7]);
    }
    __shared__ float sh[8*8];
    #pragma unroll
    for (int r=0;r<8;r++){
        #pragma unroll
        for (int o2=16;o2;o2>>=1) acc[r] += __shfl_xor_sync(0xffffffffu, acc[r], o2);
    }
    int w=tid>>5, lane=tid&31;
    if (lane==0){
        #pragma unroll
        for (int r=0;r<8;r++) sh[r*8+w]=acc[r];
    }
    __syncthreads();
    if (tid<8){
        float s=br[tid];
        #pragma unroll
        for (int ww=0;ww<8;ww++) s+=sh[tid*8+ww];
        logits[b*8+tid]=s;
    }
}

// ---------------- exact JAX threefry2x32 (partitionable) gumbel + hard select + regime lists ----------------
__device__ __forceinline__ uint32_t rotl32(uint32_t x,int r){ return (x<<r)|(x>>(32-r)); }
__device__ __forceinline__ float gumbel_from_bits(uint32_t bits){
    const float tiny = 1.17549435e-38f;
    float f = __uint_as_float((bits>>9)|0x3f800000u) - 1.0f;
    float u = fmaxf(tiny, f + tiny);
    return -logf(-logf(u));
}
__global__ void gumbel_kernel(const float* __restrict__ logits,
                              float* __restrict__ wsel,
                              int* __restrict__ rcount, int* __restrict__ rlist){
    __shared__ float g[256];
    __shared__ int sreg[BNUM];
    int tid = threadIdx.x;  // 256 threads
    {
        uint32_t x0 = 0u, x1 = (uint32_t)tid;
        const uint32_t k0=0u, k1=42u, k2=k0^k1^0x1BD11BDAu;
        x0+=k0; x1+=k1;
        #define TFR(r) { x0+=x1; x1=rotl32(x1,r); x1^=x0; }
        TFR(13)TFR(15)TFR(26)TFR(6)   x0+=k1; x1+=k2+1u;
        TFR(17)TFR(29)TFR(16)TFR(24)  x0+=k2; x1+=k0+2u;
        TFR(13)TFR(15)TFR(26)TFR(6)   x0+=k0; x1+=k1+3u;
        TFR(17)TFR(29)TFR(16)TFR(24)  x0+=k1; x1+=k2+4u;
        TFR(13)TFR(15)TFR(26)TFR(6)   x0+=k2; x1+=k0+5u;
        #undef TFR
        g[tid] = gumbel_from_bits(x0 ^ x1);
    }
    __syncthreads();
    if (tid < BNUM){
        float z[8];
        #pragma unroll
        for (int r=0;r<8;r++) z[r] = logits[tid*8+r] + g[tid*8+r];  // TAU=1
        float mx = z[0]; int am = 0;
        #pragma unroll
        for (int r=1;r<8;r++) if (z[r] > mx){ mx=z[r]; am=r; }
        float sum=0.f;
        #pragma unroll
        for (int r=0;r<8;r++) sum += expf(z[r]-mx);
        float y = 1.0f/sum;
        wsel[tid] = (1.0f - y) + y;
        sreg[tid] = am;
    }
    __syncthreads();
    if (tid == 0){
        int cnt[RNUM];
        #pragma unroll
        for (int r=0;r<RNUM;r++) cnt[r]=0;
        for (int b=0;b<BNUM;b++){
            int r = sreg[b];
            rlist[r*BNUM + cnt[r]] = b;
            cnt[r]++;
        }
        #pragma unroll
        for (int r=0;r<RNUM;r++) rcount[r]=cnt[r];
    }
}

// ---------------- final contraction, regime-grouped, f32x2 over batch pairs ----------------
template<int NP>
__device__ __forceinline__ void fp_body(const uint64_t* __restrict__ es2,
                                        const float* __restrict__ P,
                                        float* __restrict__ partial,
                                        const int* __restrict__ bl,
                                        int nb, int chunk, int t){
    uint64_t acc[NP];
    #pragma unroll
    for (int q=0;q<NP;q++) acc[q]=0ull;
    #pragma unroll 4
    for (int nh=0; nh<256; nh++){
        float pv = P[(size_t)nh*OUTC];
        uint64_t pp = pack2(pv, pv);
        const uint64_t* row = es2 + nh*16;
        #pragma unroll
        for (int q=0;q<NP;q++) ffma2(acc[q], row[q], pp, acc[q]);
    }
    #pragma unroll
    for (int q=0;q<NP;q++){
        float lo, hi; unpack2(acc[q], lo, hi);
        partial[((size_t)bl[2*q]*NCHUNK + chunk)*OUTC + t] = lo;
        if (2*q+1 < nb)
            partial[((size_t)bl[2*q+1]*NCHUNK + chunk)*OUTC + t] = hi;
    }
}

__global__ void final_partial(const float* __restrict__ est, const float* __restrict__ proto,
                              const int* __restrict__ rcount, const int* __restrict__ rlist,
                              float* __restrict__ partial){
    int chunk = blockIdx.x, r = blockIdx.y, t = threadIdx.x;  // 192 threads
    int nb = rcount[r];
    if (nb == 0) return;
    int npair = (nb+1)>>1;
    __shared__ __align__(16) uint64_t es2[256*16];   // [nh][pair] 32KB
    __shared__ int bl[BNUM];
    if (t < BNUM) bl[t] = rlist[r*BNUM + t];
    __syncthreads();
    int nh0 = chunk*256;
    for (int q=0;q<npair;q++){
        int b0 = bl[2*q];
        bool has1 = (2*q+1) < nb;
        const float* e0 = est + (size_t)b0*NHTOT + nh0;
        const float* e1 = has1 ? est + (size_t)bl[2*q+1]*NHTOT + nh0 : e0;
        for (int nh=t; nh<256; nh+=192){
            float lo = e0[nh];
            float hi = has1 ? e1[nh] : 0.f;
            es2[nh*16+q] = pack2(lo, hi);
        }
    }
    __syncthreads();
    const float* P = proto + ((size_t)r*NHTOT + nh0)*OUTC + t;
    switch(npair){
        case 1:  fp_body<1>(es2,P,partial,bl,nb,chunk,t); break;
        case 2:  fp_body<2 >(es2,P,partial,bl,nb,chunk,t); break;
        case 3:  fp_body<3 >(es2,P,partial,bl,nb,chunk,t); break;
        case 4:  fp_body<4 >(es2,P,partial,bl,nb,chunk,t); break;
        case 5:  fp_body<5 >(es2,P,partial,bl,nb,chunk,t); break;
        case 6:  fp_body<6 >(es2,P,partial,bl,nb,chunk,t); break;
        case 7:  fp_body<7 >(es2,P,partial,bl,nb,chunk,t); break;
        case 8:  fp_body<8 >(es2,P,partial,bl,nb,chunk,t); break;
        case 9:  fp_body<9 >(es2,P,partial,bl,nb,chunk,t); break;
        case 10: fp_body<10>(es2,P,partial,bl,nb,chunk,t); break;
        case 11: fp_body<11>(es2,P,partial,bl,nb,chunk,t); break;
        case 12: fp_body<12>(es2,P,partial,bl,nb,chunk,t); break;
        case 13: fp_body<13>(es2,P,partial,bl,nb,chunk,t); break;
        case 14: fp_body<14>(es2,P,partial,bl,nb,chunk,t); break;
        case 15: fp_body<15>(es2,P,partial,bl,nb,chunk,t); break;
        default: fp_body<16>(es2,P,partial,bl,nb,chunk,t); break;
    }
}

__global__ void final_softmax(const float* __restrict__ partial, const float* __restrict__ wsel,
                              float* __restrict__ out){
    int b = blockIdx.x, t = threadIdx.x;  // 192 threads = 6 warps
    float s = 0.f;
    #pragma unroll 8
    for (int ch=0; ch<NCHUNK; ch++) s += partial[((size_t)b*NCHUNK+ch)*OUTC + t];
    s *= wsel[b];
    __shared__ float shm[6], shs[6];
    float m = s;
    #pragma unroll
    for (int o=16;o;o>>=1) m = fmaxf(m, __shfl_xor_sync(0xffffffffu, m, o));
    if ((t&31)==0) shm[t>>5]=m;
    __syncthreads();
    m = shm[0];
    #pragma unroll
    for (int w=1;w<6;w++) m = fmaxf(m, shm[w]);
    float e = expf(s-m);
    float su = e;
    #pragma unroll
    for (int o=16;o;o>>=1) su += __shfl_xor_sync(0xffffffffu, su, o);
    if ((t&31)==0) shs[t>>5]=su;
    __syncthreads();
    su = 0.f;
    #pragma unroll
    for (int w=0;w<6;w++) su += shs[w];
    out[(size_t)b*OUTC + t] = e/su;
}

// ---------------- launch ----------------
extern "C" void kernel_launch(void* const* d_in, const int* in_sizes, int n_in,
                              void* d_out, int out_size){
    (void)in_sizes; (void)n_in; (void)out_size;
    const float* in_lt = (const float*)d_in[0];
    const float* in_st = (const float*)d_in[1];
    const float* Ws  = (const float*)d_in[2];  const float* bs  = (const float*)d_in[3];
    const float* Wt  = (const float*)d_in[4];  const float* bt  = (const float*)d_in[5];
    const float* Wh1 = (const float*)d_in[6];  const float* bh1 = (const float*)d_in[7];
    const float* Wl1 = (const float*)d_in[8];  const float* bl1 = (const float*)d_in[9];
    const float* Wh2 = (const float*)d_in[10]; const float* bh2 = (const float*)d_in[11];
    const float* Wl2 = (const float*)d_in[12]; const float* bl2 = (const float*)d_in[13];
    const float* Wh3 = (const float*)d_in[14]; const float* bh3 = (const float*)d_in[15];
    const float* Wl3 = (const float*)d_in[16]; const float* bl3 = (const float*)d_in[17];
    const float* Wr  = (const float*)d_in[18]; const float* br  = (const float*)d_in[19];
    const float* proto = (const float*)d_in[20];

    float *bufA, *bufB, *est, *logits, *wsel, *partial; int *rcount, *rlist;
    cudaGetSymbolAddress((void**)&bufA,    d_bufA);
    cudaGetSymbolAddress((void**)&bufB,    d_bufB);
    cudaGetSymbolAddress((void**)&est,     d_est);
    cudaGetSymbolAddress((void**)&logits,  d_logits);
    cudaGetSymbolAddress((void**)&wsel,    d_wsel);
    cudaGetSymbolAddress((void**)&rcount,  d_rcount);
    cudaGetSymbolAddress((void**)&rlist,   d_rlist);
    cudaGetSymbolAddress((void**)&partial, d_partial);

    encode_kernel<<<dim3(LLT,BNUM), HDIM>>>(in_lt, Ws, bs, Wt, bt, bufA, LLT);
    encode_kernel<<<dim3(LST,BNUM), HDIM>>>(in_st, Ws, bs, Wt, bt, est,  LST);

    hidden_kernel<<<dim3(LLT/8,BNUM), HDIM>>>(bufA, Wh1, bh1, bufB, LLT);
    lookback_kernel<512,256,1><<<dim3(32,BNUM), 256>>>(bufB, Wl1, bl1, bufA);
    hidden_kernel<<<dim3(256/8,BNUM), HDIM>>>(bufA, Wh2, bh2, bufB, 256);
    lookback_kernel<256,128,2><<<dim3(16,BNUM), 256>>>(bufB, Wl2, bl2, bufA);
    hidden_kernel<<<dim3(128/8,BNUM), HDIM>>>(bufA, Wh3, bh3, bufB, 128);
    lookback_kernel<128,64,4><<<dim3(8,BNUM), 256>>>(bufB, Wl3, bl3, bufA);

    logits_kernel<<<BNUM, 256>>>(bufA, Wr, br, logits);
    gumbel_kernel<<<1, 256>>>(logits, wsel, rcount, rlist);

    final_partial<<<dim3(NCHUNK,RNUM), OUTC>>>(est, proto, rcount, rlist, partial);
    final_softmax<<<BNUM, OUTC>>>(partial, wsel, (float*)d_out);
}